// round 7
// baseline (speedup 1.0000x reference)
#include <cuda_runtime.h>
#include <cuda_fp16.h>
#include <cstdint>

#define E_   8
#define CAP_ 2048
#define D_   1024
#define H_   4096

// ---------------- scratch (device globals; no runtime allocation) ----------------
__device__ __half g_Xh [(size_t)E_ * CAP_ * D_];   // [E*2048][1024]
__device__ __half g_W1h[(size_t)E_ * H_   * D_];   // [E*4096][1024]
__device__ __half g_W2T[(size_t)E_ * D_   * H_];   // [E*1024][4096]  (W2^T)
__device__ __half g_Y  [(size_t)E_ * CAP_ * H_];   // [E*2048][4096]

// ---------------- PTX helpers (portable: sm_80+ features only) ----------------
__device__ __forceinline__ uint32_t smem_u32(const void* p) {
    uint32_t a;
    asm("{ .reg .u64 t; cvta.to.shared.u64 t, %1; cvt.u32.u64 %0, t; }" : "=r"(a) : "l"(p));
    return a;
}
__device__ __forceinline__ void cpa16(uint32_t s, const void* g) {
    asm volatile("cp.async.cg.shared.global [%0], [%1], 16;" :: "r"(s), "l"(g) : "memory");
}
__device__ __forceinline__ void ldsm4(uint32_t r[4], uint32_t addr) {
    asm volatile("ldmatrix.sync.aligned.m8n8.x4.shared.b16 {%0,%1,%2,%3}, [%4];"
                 : "=r"(r[0]), "=r"(r[1]), "=r"(r[2]), "=r"(r[3]) : "r"(addr));
}
__device__ __forceinline__ void mma16816(float d[4], const uint32_t a[4],
                                         uint32_t b0, uint32_t b1) {
    asm volatile("mma.sync.aligned.m16n8k16.row.col.f32.f16.f16.f32 "
                 "{%0,%1,%2,%3},{%4,%5,%6,%7},{%8,%9},{%0,%1,%2,%3};"
                 : "+f"(d[0]), "+f"(d[1]), "+f"(d[2]), "+f"(d[3])
                 : "r"(a[0]), "r"(a[1]), "r"(a[2]), "r"(a[3]), "r"(b0), "r"(b1));
}
__device__ __forceinline__ uint32_t h2u(__half2 h) {
    return *reinterpret_cast<uint32_t*>(&h);
}

// ---------------- convert: fp32 -> fp16 elementwise; dst chosen in DEVICE code ----------------
template<int TGT>   // 0 -> g_Xh, 1 -> g_W1h
__global__ void conv_f16(const float* __restrict__ src) {
    __half* dst = (TGT == 0) ? g_Xh : g_W1h;
    size_t t = (size_t)blockIdx.x * 256 + threadIdx.x;   // one float4 per thread
    float4 v = *((const float4*)src + t);
    __half2 h0 = __floats2half2_rn(v.x, v.y);
    __half2 h1 = __floats2half2_rn(v.z, v.w);
    *(uint2*)(dst + t * 4) = make_uint2(h2u(h0), h2u(h1));
}

// ---------------- W2 transpose + convert: [E,H,D] fp32 -> [E,D][H] fp16 ----------------
__global__ void conv_w2t(const float* __restrict__ w2) {
    __shared__ float tile[32][33];
    int e  = blockIdx.z;
    int d0 = blockIdx.x * 32;
    int h0 = blockIdx.y * 32;
    int tx = threadIdx.x, ty = threadIdx.y;
#pragma unroll
    for (int r = 0; r < 4; r++) {
        int h = h0 + ty + r * 8;
        tile[ty + r * 8][tx] = w2[((size_t)(e * H_ + h)) * D_ + d0 + tx];
    }
    __syncthreads();
#pragma unroll
    for (int r = 0; r < 4; r++) {
        int d = d0 + ty + r * 8;
        int h = h0 + tx;
        g_W2T[((size_t)(e * D_ + d)) * H_ + h] = __float2half_rn(tile[tx][ty + r * 8]);
    }
}

// ---------------- fp16 GEMM via mma.sync (cp.async pipeline), tunable tiles ----------------
// PHASE 1: g_Xh[2048,K] x g_W1h[4096,K]^T -> relu(+b1) -> g_Y (fp16)
// PHASE 2: g_Y[2048,K'] x g_W2T[1024,K']^T -> +b2 -> outF (fp32)
// Warp grid fixed at 4 (M) x 2 (N): TM/WM == 4, TN/WN == 2.
template<int PHASE, int TM, int TN, int WM, int WN, int NSTAGE, int MINB>
__global__ void __launch_bounds__(256, MINB) gemm_mma(const float* __restrict__ bias,
                                                      float* __restrict__ outF) {
    static_assert(TM / WM == 4 && TN / WN == 2, "warp grid must be 4x2");
    constexpr int Ntot = (PHASE == 1) ? H_ : D_;
    constexpr int KSEG = (PHASE == 1) ? D_ : H_;
    constexpr int NCH  = KSEG / 64;        // 64-wide K chunks
    constexpr int Mt   = CAP_ / TM;
    constexpr int Nt   = Ntot / TN;
    constexpr int STB  = (TM + TN) * 128;  // per-stage bytes
    constexpr int WROWS = WM / 16, WCOLS = WN / 8, BT16 = WN / 16;

    extern __shared__ char smem[];
    const uint32_t sb = smem_u32(smem);
    const int tid = threadIdx.x, wid = tid >> 5, lane = tid & 31;

    const int idx = blockIdx.x;
    const int mt = idx % Mt;
    const int nt = (idx / Mt) % Nt;
    const int e  = idx / (Mt * Nt);
    const int m0 = mt * TM, n0 = nt * TN;

    const __half* A = (PHASE == 1) ? g_Xh  : g_Y;
    const __half* B = (PHASE == 1) ? g_W1h : g_W2T;
    const __half* Ab = A + (size_t)(e * CAP_ + m0) * KSEG;
    const __half* Bb = B + (size_t)(e * Ntot + n0) * KSEG;

    auto issue = [&](int c) {
        const int k0 = c * 64;
        const int st = c % NSTAGE;
        const uint32_t sA = sb + st * STB, sB = sA + TM * 128;
#pragma unroll
        for (int t = 0; t < TM / 32; t++) {
            int i = t * 256 + tid, row = i >> 3, c16 = i & 7;
            cpa16(sA + row * 128 + ((c16 ^ (row & 7)) << 4),
                  Ab + (size_t)row * KSEG + k0 + c16 * 8);
        }
#pragma unroll
        for (int t = 0; t < TN / 32; t++) {
            int i = t * 256 + tid, row = i >> 3, c16 = i & 7;
            cpa16(sB + row * 128 + ((c16 ^ (row & 7)) << 4),
                  Bb + (size_t)row * KSEG + k0 + c16 * 8);
        }
        asm volatile("cp.async.commit_group;" ::: "memory");
    };

    const int m_off = (wid >> 1) * WM;
    const int n_off = (wid & 1) * WN;
    float acc[WROWS][WCOLS][4] = {};

#pragma unroll
    for (int s = 0; s < NSTAGE - 1; s++) issue(s);
    asm volatile("cp.async.wait_group %0;" :: "n"(NSTAGE - 2));
    __syncthreads();

    for (int c = 0; c < NCH; ++c) {
        const int st = c % NSTAGE;
        const uint32_t sA = sb + st * STB, sB = sA + TM * 128;
#pragma unroll
        for (int kk = 0; kk < 4; ++kk) {               // 4 x k16 per 64-chunk
            uint32_t aF[WROWS][4];
#pragma unroll
            for (int i = 0; i < WROWS; ++i) {
                int row = m_off + 16 * i + (lane & 15);
                int ch  = kk * 2 + (lane >> 4);
                ldsm4(aF[i], sA + row * 128 + ((ch ^ (row & 7)) << 4));
            }
            uint32_t bF[BT16][4];
#pragma unroll
            for (int j4 = 0; j4 < BT16; ++j4) {
                int row = n_off + 16 * j4 + ((lane >> 4) << 3) + (lane & 7);
                int ch  = kk * 2 + ((lane >> 3) & 1);
                ldsm4(bF[j4], sB + row * 128 + ((ch ^ (row & 7)) << 4));
            }
#pragma unroll
            for (int i = 0; i < WROWS; ++i)
#pragma unroll
                for (int j = 0; j < WCOLS; ++j)
                    mma16816(acc[i][j], aF[i], bF[j >> 1][(j & 1) * 2], bF[j >> 1][(j & 1) * 2 + 1]);
        }
        if (c + NSTAGE - 1 < NCH) issue(c + NSTAGE - 1);
        else asm volatile("cp.async.commit_group;" ::: "memory");
        asm volatile("cp.async.wait_group %0;" :: "n"(NSTAGE - 2));
        __syncthreads();
    }

    // ---- epilogue ----
    const int r_lane = lane >> 2;
    const int c_lane = (lane & 3) * 2;
    const float* brow = bias + (size_t)e * Ntot;
#pragma unroll
    for (int i = 0; i < WROWS; ++i) {
#pragma unroll
        for (int half = 0; half < 2; ++half) {
            const int m = m0 + m_off + 16 * i + r_lane + half * 8;
            if (PHASE == 1) {
                __half* yrow = g_Y + (size_t)(e * CAP_ + m) * H_;
#pragma unroll
                for (int j = 0; j < WCOLS; ++j) {
                    const int col = n0 + n_off + 8 * j + c_lane;
                    float v0 = acc[i][j][half * 2 + 0] + brow[col];
                    float v1 = acc[i][j][half * 2 + 1] + brow[col + 1];
                    v0 = fmaxf(v0, 0.f);
                    v1 = fmaxf(v1, 0.f);
                    *(uint32_t*)(yrow + col) = h2u(__floats2half2_rn(v0, v1));
                }
            } else {
                float* orow = outF + (size_t)(e * CAP_ + m) * D_;
#pragma unroll
                for (int j = 0; j < WCOLS; ++j) {
                    const int col = n0 + n_off + 8 * j + c_lane;
                    float2 f;
                    f.x = acc[i][j][half * 2 + 0] + brow[col];
                    f.y = acc[i][j][half * 2 + 1] + brow[col + 1];
                    *(float2*)(orow + col) = f;
                }
            }
        }
    }
}

// ---------------- launch ----------------
extern "C" void kernel_launch(void* const* d_in, const int* in_sizes, int n_in,
                              void* d_out, int out_size) {
    const float* x  = (const float*)d_in[0];   // [E, CAP, D]
    const float* w1 = (const float*)d_in[1];   // [E, H, D]
    const float* b1 = (const float*)d_in[2];   // [E, H]
    const float* w2 = (const float*)d_in[3];   // [E, H, D]
    const float* b2 = (const float*)d_in[4];   // [E, D]
    float* out = (float*)d_out;                // [E, CAP, D]

    // GEMM1: 256x128 CTA tile, 64x64 warp tile, 4 stages, 1 CTA/SM  (192 KB smem)
    auto g1 = gemm_mma<1, 256, 128, 64, 64, 4, 1>;
    constexpr int SM1 = 4 * (256 + 128) * 128;            // 196608
    // GEMM2: 128x64 CTA tile, 32x32 warp tile, 3 stages, 2 CTAs/SM  (72 KB smem)
    auto g2 = gemm_mma<2, 128, 64, 32, 32, 3, 2>;
    constexpr int SM2 = 3 * (128 + 64) * 128;             // 73728

    cudaFuncSetAttribute(g1, cudaFuncAttributeMaxDynamicSharedMemorySize, SM1);
    cudaFuncSetAttribute(g2, cudaFuncAttributeMaxDynamicSharedMemorySize, SM2);

    // 1) conversions (destinations resolved in device code)
    conv_f16<0><<<(E_ * CAP_ * D_ / 4) / 256, 256>>>(x);           // X  -> g_Xh
    conv_f16<1><<<(E_ * H_   * D_ / 4) / 256, 256>>>(w1);          // W1 -> g_W1h
    conv_w2t<<<dim3(D_ / 32, H_ / 32, E_), dim3(32, 8)>>>(w2);     // W2 -> g_W2T (transposed)

    // 2) GEMM1: relu(X W1^T + b1) -> g_Y (fp16)
    g1<<<(CAP_ / 256) * (H_ / 128) * E_, 256, SM1>>>(b1, nullptr);

    // 3) GEMM2: Y W2 + b2 -> out (fp32)
    g2<<<(CAP_ / 128) * (D_ / 64) * E_, 256, SM2>>>(b2, out);
}

// round 8
// speedup vs baseline: 1.1250x; 1.1250x over previous
#include <cuda_runtime.h>
#include <cuda_fp16.h>
#include <cstdint>

#define E_   8
#define CAP_ 2048
#define D_   1024
#define H_   4096

// ---------------- scratch (device globals; no runtime allocation) ----------------
__device__ __half g_Xh [(size_t)E_ * CAP_ * D_];   // [E*2048][1024]
__device__ __half g_W1h[(size_t)E_ * H_   * D_];   // [E*4096][1024]
__device__ __half g_W2T[(size_t)E_ * D_   * H_];   // [E*1024][4096]  (W2^T)
__device__ __half g_Y  [(size_t)E_ * CAP_ * H_];   // [E*2048][4096]

// ---------------- PTX helpers (portable: sm_80+ features only) ----------------
__device__ __forceinline__ uint32_t smem_u32(const void* p) {
    uint32_t a;
    asm("{ .reg .u64 t; cvta.to.shared.u64 t, %1; cvt.u32.u64 %0, t; }" : "=r"(a) : "l"(p));
    return a;
}
__device__ __forceinline__ void cpa16(uint32_t s, const void* g) {
    asm volatile("cp.async.cg.shared.global [%0], [%1], 16;" :: "r"(s), "l"(g) : "memory");
}
__device__ __forceinline__ void ldsm4(uint32_t r[4], uint32_t addr) {
    asm volatile("ldmatrix.sync.aligned.m8n8.x4.shared.b16 {%0,%1,%2,%3}, [%4];"
                 : "=r"(r[0]), "=r"(r[1]), "=r"(r[2]), "=r"(r[3]) : "r"(addr));
}
__device__ __forceinline__ void mma16816(float d[4], const uint32_t a[4],
                                         uint32_t b0, uint32_t b1) {
    asm volatile("mma.sync.aligned.m16n8k16.row.col.f32.f16.f16.f32 "
                 "{%0,%1,%2,%3},{%4,%5,%6,%7},{%8,%9},{%0,%1,%2,%3};"
                 : "+f"(d[0]), "+f"(d[1]), "+f"(d[2]), "+f"(d[3])
                 : "r"(a[0]), "r"(a[1]), "r"(a[2]), "r"(a[3]), "r"(b0), "r"(b1));
}
__device__ __forceinline__ uint32_t h2u(__half2 h) {
    return *reinterpret_cast<uint32_t*>(&h);
}

// ---------------- convert: fp32 -> fp16 elementwise; dst chosen in DEVICE code ----------------
template<int TGT>   // 0 -> g_Xh, 1 -> g_W1h
__global__ void conv_f16(const float* __restrict__ src) {
    __half* dst = (TGT == 0) ? g_Xh : g_W1h;
    size_t t = (size_t)blockIdx.x * 256 + threadIdx.x;   // one float4 per thread
    float4 v = *((const float4*)src + t);
    __half2 h0 = __floats2half2_rn(v.x, v.y);
    __half2 h1 = __floats2half2_rn(v.z, v.w);
    *(uint2*)(dst + t * 4) = make_uint2(h2u(h0), h2u(h1));
}

// ---------------- W2 transpose + convert: [E,H,D] fp32 -> [E,D][H] fp16 ----------------
__global__ void conv_w2t(const float* __restrict__ w2) {
    __shared__ float tile[32][33];
    int e  = blockIdx.z;
    int d0 = blockIdx.x * 32;
    int h0 = blockIdx.y * 32;
    int tx = threadIdx.x, ty = threadIdx.y;
#pragma unroll
    for (int r = 0; r < 4; r++) {
        int h = h0 + ty + r * 8;
        tile[ty + r * 8][tx] = w2[((size_t)(e * H_ + h)) * D_ + d0 + tx];
    }
    __syncthreads();
#pragma unroll
    for (int r = 0; r < 4; r++) {
        int d = d0 + ty + r * 8;
        int h = h0 + tx;
        g_W2T[((size_t)(e * D_ + d)) * H_ + h] = __float2half_rn(tile[tx][ty + r * 8]);
    }
}

// ---------------- fp16 GEMM via mma.sync (cp.async pipeline) ----------------
// 128x128 CTA tile, 4 warps (2x2 grid) of 64x64 warp tiles, 128 threads,
// 3 stages (96 KB smem) -> 2 CTAs/SM.
// PHASE 1: g_Xh[2048,K] x g_W1h[4096,K]^T -> relu(+b1) -> g_Y (fp16)
// PHASE 2: g_Y[2048,K'] x g_W2T[1024,K']^T -> +b2 -> outF (fp32)
#define TM 128
#define TN 128
#define WM 64
#define WN 64
#define NSTAGE 3
#define STB ((TM + TN) * 128)              // 32 KB per stage
#define SMEM_TOT (NSTAGE * STB)            // 96 KB

template<int PHASE>
__global__ void __launch_bounds__(128, 2) gemm_mma(const float* __restrict__ bias,
                                                   float* __restrict__ outF) {
    constexpr int Ntot = (PHASE == 1) ? H_ : D_;
    constexpr int KSEG = (PHASE == 1) ? D_ : H_;
    constexpr int NCH  = KSEG / 64;        // 64-wide K chunks
    constexpr int Mt   = CAP_ / TM;
    constexpr int Nt   = Ntot / TN;
    constexpr int WROWS = WM / 16, WCOLS = WN / 8, BT16 = WN / 16;

    extern __shared__ char smem[];
    const uint32_t sb = smem_u32(smem);
    const int tid = threadIdx.x, wid = tid >> 5, lane = tid & 31;

    const int idx = blockIdx.x;
    const int mt = idx % Mt;
    const int nt = (idx / Mt) % Nt;
    const int e  = idx / (Mt * Nt);
    const int m0 = mt * TM, n0 = nt * TN;

    const __half* A = (PHASE == 1) ? g_Xh  : g_Y;
    const __half* B = (PHASE == 1) ? g_W1h : g_W2T;
    const __half* Ab = A + (size_t)(e * CAP_ + m0) * KSEG;
    const __half* Bb = B + (size_t)(e * Ntot + n0) * KSEG;

    auto issue = [&](int c) {
        const int k0 = c * 64;
        const int st = c % NSTAGE;
        const uint32_t sA = sb + st * STB, sB = sA + TM * 128;
#pragma unroll
        for (int t = 0; t < TM / 16; t++) {            // A: TM*8 chunks / 128 thr
            int i = t * 128 + tid, row = i >> 3, c16 = i & 7;
            cpa16(sA + row * 128 + ((c16 ^ (row & 7)) << 4),
                  Ab + (size_t)row * KSEG + k0 + c16 * 8);
        }
#pragma unroll
        for (int t = 0; t < TN / 16; t++) {            // B: TN*8 chunks / 128 thr
            int i = t * 128 + tid, row = i >> 3, c16 = i & 7;
            cpa16(sB + row * 128 + ((c16 ^ (row & 7)) << 4),
                  Bb + (size_t)row * KSEG + k0 + c16 * 8);
        }
        asm volatile("cp.async.commit_group;" ::: "memory");
    };

    const int m_off = (wid >> 1) * WM;     // 2x2 warp grid
    const int n_off = (wid & 1) * WN;
    float acc[WROWS][WCOLS][4] = {};

#pragma unroll
    for (int s = 0; s < NSTAGE - 1; s++) issue(s);
    asm volatile("cp.async.wait_group %0;" :: "n"(NSTAGE - 2));
    __syncthreads();

    for (int c = 0; c < NCH; ++c) {
        const int st = c % NSTAGE;
        const uint32_t sA = sb + st * STB, sB = sA + TM * 128;
#pragma unroll
        for (int kk = 0; kk < 4; ++kk) {               // 4 x k16 per 64-chunk
            uint32_t aF[WROWS][4];
#pragma unroll
            for (int i = 0; i < WROWS; ++i) {
                int row = m_off + 16 * i + (lane & 15);
                int ch  = kk * 2 + (lane >> 4);
                ldsm4(aF[i], sA + row * 128 + ((ch ^ (row & 7)) << 4));
            }
            uint32_t bF[BT16][4];
#pragma unroll
            for (int j4 = 0; j4 < BT16; ++j4) {
                int row = n_off + 16 * j4 + ((lane >> 4) << 3) + (lane & 7);
                int ch  = kk * 2 + ((lane >> 3) & 1);
                ldsm4(bF[j4], sB + row * 128 + ((ch ^ (row & 7)) << 4));
            }
#pragma unroll
            for (int i = 0; i < WROWS; ++i)
#pragma unroll
                for (int j = 0; j < WCOLS; ++j)
                    mma16816(acc[i][j], aF[i], bF[j >> 1][(j & 1) * 2], bF[j >> 1][(j & 1) * 2 + 1]);
        }
        if (c + NSTAGE - 1 < NCH) issue(c + NSTAGE - 1);
        else asm volatile("cp.async.commit_group;" ::: "memory");
        asm volatile("cp.async.wait_group %0;" :: "n"(NSTAGE - 2));
        __syncthreads();
    }

    // ---- epilogue ----
    const int r_lane = lane >> 2;
    const int c_lane = (lane & 3) * 2;
    const float* brow = bias + (size_t)e * Ntot;
#pragma unroll
    for (int i = 0; i < WROWS; ++i) {
#pragma unroll
        for (int half = 0; half < 2; ++half) {
            const int m = m0 + m_off + 16 * i + r_lane + half * 8;
            if (PHASE == 1) {
                __half* yrow = g_Y + (size_t)(e * CAP_ + m) * H_;
#pragma unroll
                for (int j = 0; j < WCOLS; ++j) {
                    const int col = n0 + n_off + 8 * j + c_lane;
                    float v0 = acc[i][j][half * 2 + 0] + brow[col];
                    float v1 = acc[i][j][half * 2 + 1] + brow[col + 1];
                    v0 = fmaxf(v0, 0.f);
                    v1 = fmaxf(v1, 0.f);
                    *(uint32_t*)(yrow + col) = h2u(__floats2half2_rn(v0, v1));
                }
            } else {
                float* orow = outF + (size_t)(e * CAP_ + m) * D_;
#pragma unroll
                for (int j = 0; j < WCOLS; ++j) {
                    const int col = n0 + n_off + 8 * j + c_lane;
                    float2 f;
                    f.x = acc[i][j][half * 2 + 0] + brow[col];
                    f.y = acc[i][j][half * 2 + 1] + brow[col + 1];
                    *(float2*)(orow + col) = f;
                }
            }
        }
    }
}

// ---------------- launch ----------------
extern "C" void kernel_launch(void* const* d_in, const int* in_sizes, int n_in,
                              void* d_out, int out_size) {
    const float* x  = (const float*)d_in[0];   // [E, CAP, D]
    const float* w1 = (const float*)d_in[1];   // [E, H, D]
    const float* b1 = (const float*)d_in[2];   // [E, H]
    const float* w2 = (const float*)d_in[3];   // [E, H, D]
    const float* b2 = (const float*)d_in[4];   // [E, D]
    float* out = (float*)d_out;                // [E, CAP, D]

    cudaFuncSetAttribute(gemm_mma<1>, cudaFuncAttributeMaxDynamicSharedMemorySize, SMEM_TOT);
    cudaFuncSetAttribute(gemm_mma<2>, cudaFuncAttributeMaxDynamicSharedMemorySize, SMEM_TOT);

    // 1) conversions (destinations resolved in device code)
    conv_f16<0><<<(E_ * CAP_ * D_ / 4) / 256, 256>>>(x);           // X  -> g_Xh
    conv_f16<1><<<(E_ * H_   * D_ / 4) / 256, 256>>>(w1);          // W1 -> g_W1h
    conv_w2t<<<dim3(D_ / 32, H_ / 32, E_), dim3(32, 8)>>>(w2);     // W2 -> g_W2T (transposed)

    // 2) GEMM1: relu(X W1^T + b1) -> g_Y (fp16)
    gemm_mma<1><<<(CAP_ / TM) * (H_ / TN) * E_, 128, SMEM_TOT>>>(b1, nullptr);

    // 3) GEMM2: Y W2 + b2 -> out (fp32)
    gemm_mma<2><<<(CAP_ / TM) * (D_ / TN) * E_, 128, SMEM_TOT>>>(b2, out);
}